// round 1
// baseline (speedup 1.0000x reference)
#include <cuda_runtime.h>
#include <cstdint>

// GTN collapses: softmax over singleton axis == 1, so gtconv(A,w) == 2*A.
//   H  = 4*(A@A) + I
//   inv[i] = 2 / deg(H)[i]   (deg guarded at 1e-10)
//   out = diag(inv) @ (H @ A)
// Two 2048^3 fp32 GEMMs + a rowsum. fp32 via packed fma.rn.f32x2.

#define NMAT 2048

static constexpr int BM = 128;
static constexpr int BN = 128;
static constexpr int BK = 16;

// Scratch (device globals: allocation-free per harness rules)
__device__ float g_H[(size_t)NMAT * NMAT];
__device__ float g_inv[NMAT];

template <int MODE>
__launch_bounds__(256, 2)
__global__ void gemm_kernel(const float* __restrict__ A_in, float* __restrict__ Cout)
{
    // MODE 0: C = 4*(A_in @ A_in) + I   -> g_H
    // MODE 1: C = diag(g_inv) @ (g_H @ A_in) -> Cout
    const float* Ag = (MODE == 0) ? A_in : (const float*)g_H;  // left operand
    const float* Bg = A_in;                                    // right operand (always A)
    float*       Cg = (MODE == 0) ? (float*)g_H : Cout;

    __shared__ __align__(16) float As[2][BK][BM + 4];  // stride 132: breaks STS conflicts, keeps 16B align
    __shared__ __align__(16) float Bs[2][BK][BN];

    const int tid = threadIdx.x;
    const int tx = tid & 15;        // N direction (8 cols each)
    const int ty = tid >> 4;        // M direction (8 rows each)
    const int row0 = blockIdx.y * BM;
    const int col0 = blockIdx.x * BN;

    // A-tile loader: thread -> (row ar / ar+64, 4 consecutive k at ac)
    const int ar = tid >> 2;            // 0..63
    const int ac = (tid & 3) << 2;      // 0,4,8,12
    // B-tile loader: warp bw handles rows bw and bw+8, lane covers 4 consecutive cols
    const int blane = tid & 31;
    const int bw = tid >> 5;            // 0..7

    const float* Aptr = Ag + (size_t)(row0 + ar) * NMAT + ac;
    const float* Bptr = Bg + (size_t)bw * NMAT + col0 + blane * 4;

    float4 a_st0, a_st1, b_st0, b_st1;

    // Prologue: load k-tile 0 into buffer 0
    a_st0 = *(const float4*)(Aptr);
    a_st1 = *(const float4*)(Aptr + (size_t)64 * NMAT);
    b_st0 = *(const float4*)(Bptr);
    b_st1 = *(const float4*)(Bptr + (size_t)8 * NMAT);
    {
        As[0][ac + 0][ar]      = a_st0.x; As[0][ac + 1][ar]      = a_st0.y;
        As[0][ac + 2][ar]      = a_st0.z; As[0][ac + 3][ar]      = a_st0.w;
        As[0][ac + 0][ar + 64] = a_st1.x; As[0][ac + 1][ar + 64] = a_st1.y;
        As[0][ac + 2][ar + 64] = a_st1.z; As[0][ac + 3][ar + 64] = a_st1.w;
        *(float4*)&Bs[0][bw][blane * 4]     = b_st0;
        *(float4*)&Bs[0][bw + 8][blane * 4] = b_st1;
    }
    __syncthreads();

    // Accumulators: 8 rows x 4 packed f32x2 pairs (= 8x8 fp32)
    unsigned long long acc[8][4];
#pragma unroll
    for (int m = 0; m < 8; m++)
#pragma unroll
        for (int p = 0; p < 4; p++) acc[m][p] = 0ull;

    const int nk = NMAT / BK;  // 128
    for (int kt = 0; kt < nk; ++kt) {
        const int buf = kt & 1;

        // Prefetch next k-tile global -> registers
        if (kt + 1 < nk) {
            const float* Ap = Aptr + (size_t)(kt + 1) * BK;
            const float* Bp = Bptr + (size_t)(kt + 1) * BK * NMAT;
            a_st0 = *(const float4*)(Ap);
            a_st1 = *(const float4*)(Ap + (size_t)64 * NMAT);
            b_st0 = *(const float4*)(Bp);
            b_st1 = *(const float4*)(Bp + (size_t)8 * NMAT);
        }

#pragma unroll
        for (int k = 0; k < BK; k++) {
            const float4 a0 = *(const float4*)&As[buf][k][ty * 8];
            const float4 a1 = *(const float4*)&As[buf][k][ty * 8 + 4];
            const ulonglong2 bq0 = *(const ulonglong2*)&Bs[buf][k][tx * 8];
            const ulonglong2 bq1 = *(const ulonglong2*)&Bs[buf][k][tx * 8 + 4];
            const unsigned long long bp[4] = {bq0.x, bq0.y, bq1.x, bq1.y};
            const float av[8] = {a0.x, a0.y, a0.z, a0.w, a1.x, a1.y, a1.z, a1.w};
#pragma unroll
            for (int m = 0; m < 8; m++) {
                unsigned long long ad;
                asm("mov.b64 %0, {%1, %1};" : "=l"(ad) : "f"(av[m]));
#pragma unroll
                for (int p = 0; p < 4; p++) {
                    asm("fma.rn.f32x2 %0, %1, %2, %0;"
                        : "+l"(acc[m][p])
                        : "l"(ad), "l"(bp[p]));
                }
            }
        }

        // Stage next tile into the other buffer (safe: everyone finished it last iter)
        if (kt + 1 < nk) {
            const int nb = buf ^ 1;
            As[nb][ac + 0][ar]      = a_st0.x; As[nb][ac + 1][ar]      = a_st0.y;
            As[nb][ac + 2][ar]      = a_st0.z; As[nb][ac + 3][ar]      = a_st0.w;
            As[nb][ac + 0][ar + 64] = a_st1.x; As[nb][ac + 1][ar + 64] = a_st1.y;
            As[nb][ac + 2][ar + 64] = a_st1.z; As[nb][ac + 3][ar + 64] = a_st1.w;
            *(float4*)&Bs[nb][bw][blane * 4]     = b_st0;
            *(float4*)&Bs[nb][bw + 8][blane * 4] = b_st1;
        }
        __syncthreads();
    }

    // Epilogue
#pragma unroll
    for (int m = 0; m < 8; m++) {
        const int r = row0 + ty * 8 + m;
        const float scale = (MODE == 0) ? 4.0f : g_inv[r];
        float o[8];
#pragma unroll
        for (int p = 0; p < 4; p++) {
            float lo, hi;
            asm("mov.b64 {%0, %1}, %2;" : "=f"(lo), "=f"(hi) : "l"(acc[m][p]));
            o[2 * p]     = scale * lo;
            o[2 * p + 1] = scale * hi;
        }
        if (MODE == 0) {
            const int cbase = col0 + tx * 8;
            if (r >= cbase && r < cbase + 8) o[r - cbase] += 1.0f;  // + I
        }
        float4* dst = (float4*)(Cg + (size_t)r * NMAT + col0 + tx * 8);
        dst[0] = make_float4(o[0], o[1], o[2], o[3]);
        dst[1] = make_float4(o[4], o[5], o[6], o[7]);
    }
}

__global__ void rowsum_kernel()
{
    __shared__ float red[256];
    const int row = blockIdx.x;
    const float4* p = (const float4*)(g_H + (size_t)row * NMAT);
    float s = 0.f;
    for (int i = threadIdx.x; i < NMAT / 4; i += 256) {
        const float4 v = p[i];
        s += (v.x + v.y) + (v.z + v.w);
    }
    red[threadIdx.x] = s;
    __syncthreads();
#pragma unroll
    for (int off = 128; off > 0; off >>= 1) {
        if (threadIdx.x < off) red[threadIdx.x] += red[threadIdx.x + off];
        __syncthreads();
    }
    if (threadIdx.x == 0) {
        float d = red[0];
        if (d <= 1e-10f) d = 1.f;
        g_inv[row] = 2.f / d;   // folds the final factor of 2
    }
}

extern "C" void kernel_launch(void* const* d_in, const int* in_sizes, int n_in,
                              void* d_out, int out_size)
{
    const float* A = (const float*)d_in[0];   // (2048, 2048) fp32; weights d_in[1..3] unused (softmax==1)
    float* out = (float*)d_out;               // (1, 2048, 2048) fp32

    dim3 grid(NMAT / BN, NMAT / BM);
    dim3 block(256);

    gemm_kernel<0><<<grid, block>>>(A, out);   // H = 4*A@A + I -> g_H
    rowsum_kernel<<<NMAT, 256>>>();            // g_inv = 2/deg
    gemm_kernel<1><<<grid, block>>>(A, out);   // out = diag(g_inv) @ (H @ A)
}

// round 3
// speedup vs baseline: 6.8690x; 6.8690x over previous
#include <cuda_runtime.h>
#include <cuda_bf16.h>
#include <cstdint>

// GTN collapses (softmax over singleton axis == 1 -> gtconv == 2*A):
//   H   = 4*(A@A) + I
//   inv = 2 / rowsum(H)   (guarded)
//   out = diag(inv) @ (H @ A)
// tcgen05 is unavailable (harness PTX targets sm_103 without the 'a' feature),
// so both 2048^3 GEMMs run on mma.sync bf16 HMMA with cp.async pipelines.

#define NMAT 2048
static constexpr int BM = 128;
static constexpr int BN = 128;
static constexpr int BK = 32;
static constexpr int STAGES = 4;
static constexpr int KT = NMAT / BK;            // 64
static constexpr int STAGE_BYTES = BM * 64;     // 8KB (rows of 32 bf16 = 64B)
static constexpr int SMEM_B_OFF = STAGES * STAGE_BYTES;      // 32KB
static constexpr int SMEM_DYN = 2 * STAGES * STAGE_BYTES;    // 64KB

// Device scratch (allocation-free per harness rules)
__device__ __nv_bfloat16 g_Abf[(size_t)NMAT * NMAT];
__device__ __nv_bfloat16 g_ATbf[(size_t)NMAT * NMAT];
__device__ __nv_bfloat16 g_Hbf[(size_t)NMAT * NMAT];
__device__ float g_rowpart[2][NMAT / BN][NMAT];
__device__ float g_inv[NMAT];

__device__ __forceinline__ uint32_t smem_u32(const void* p) {
    uint32_t a;
    asm("{ .reg .u64 t; cvta.to.shared.u64 t, %1; cvt.u32.u64 %0, t; }" : "=r"(a) : "l"(p));
    return a;
}
#define CP_ASYNC16(dst, src) asm volatile("cp.async.cg.shared.global [%0], [%1], 16;" :: "r"(dst), "l"(src) : "memory")
#define CP_COMMIT()          asm volatile("cp.async.commit_group;" ::: "memory")
#define CP_WAIT2()           asm volatile("cp.async.wait_group 2;" ::: "memory")
#define LDSM_X4(r0, r1, r2, r3, a) \
    asm volatile("ldmatrix.sync.aligned.m8n8.x4.shared.b16 {%0,%1,%2,%3}, [%4];" \
                 : "=r"(r0), "=r"(r1), "=r"(r2), "=r"(r3) : "r"(a))
#define MMA_BF16(c, a, b) \
    asm volatile("mma.sync.aligned.m16n8k16.row.col.f32.bf16.bf16.f32 " \
                 "{%0,%1,%2,%3}, {%4,%5,%6,%7}, {%8,%9}, {%0,%1,%2,%3};" \
                 : "+f"((c)[0]), "+f"((c)[1]), "+f"((c)[2]), "+f"((c)[3]) \
                 : "r"((a)[0]), "r"((a)[1]), "r"((a)[2]), "r"((a)[3]), "r"((b)[0]), "r"((b)[1]))

// Swizzled byte offset inside a stage: rows are 64B; XOR keeps LDSM/STS conflict-free.
__device__ __forceinline__ uint32_t swz(int row, int colb) {
    return (uint32_t)(row * 64 + (colb ^ (((row >> 1) & 3) << 4)));
}

// ---------------- A -> bf16 and A^T -> bf16 ----------------
__global__ void convert_kernel(const float* __restrict__ A)
{
    __shared__ float t[32][33];
    const int tx = threadIdx.x, ty = threadIdx.y;
    const int x = blockIdx.x * 32 + tx;
    const int y0 = blockIdx.y * 32;
#pragma unroll
    for (int j = 0; j < 32; j += 8) {
        const int row = y0 + j + ty;
        const float v = A[(size_t)row * NMAT + x];
        t[j + ty][tx] = v;
        g_Abf[(size_t)row * NMAT + x] = __float2bfloat16(v);
    }
    __syncthreads();
    const int nx = y0 + tx;
#pragma unroll
    for (int j = 0; j < 32; j += 8) {
        const int orow = blockIdx.x * 32 + j + ty;
        g_ATbf[(size_t)orow * NMAT + nx] = __float2bfloat16(t[tx][j + ty]);
    }
}

__global__ void invdeg_kernel()
{
    const int r = blockIdx.x * 256 + threadIdx.x;
    float d = 0.f;
#pragma unroll
    for (int h = 0; h < 2; h++)
#pragma unroll
        for (int t = 0; t < NMAT / BN; t++) d += g_rowpart[h][t][r];
    if (d <= 1e-10f) d = 1.f;
    g_inv[r] = 2.f / d;
}

// ---------------- HMMA GEMM:  D = L @ (A^T)^T  (both operands K-major) ----------------
// MODE 0: L = g_Abf ; epilogue H = 4D + I -> g_Hbf (+ row partials)
// MODE 1: L = g_Hbf ; epilogue out = g_inv[r] * D (fp32)
template <int MODE>
__launch_bounds__(256, 2)
__global__ void gemm_mma(float* __restrict__ Cout)
{
    extern __shared__ char dyn_raw[];
    const uint32_t sb = smem_u32(dyn_raw);

    const int tid = threadIdx.x;
    const int lane = tid & 31;
    const int wid = tid >> 5;
    const int warp_m = wid & 3;        // 4 warps down M, 32 rows each
    const int warp_n = wid >> 2;       // 2 warps across N, 64 cols each
    const int row0 = blockIdx.y * BM;
    const int col0 = blockIdx.x * BN;

    const __nv_bfloat16* __restrict__ Lop = (MODE == 0) ? g_Abf : g_Hbf;
    const __nv_bfloat16* __restrict__ Rop = g_ATbf;

    // cp.async fill of k-tile kt into stage s (A: 512 chunks, B: 512 chunks; 4/thread)
    auto fill = [&](int kt, int s) {
        const uint32_t ab = sb + s * STAGE_BYTES;
        const uint32_t bb = sb + SMEM_B_OFF + s * STAGE_BYTES;
#pragma unroll
        for (int i = 0; i < 2; i++) {
            const int ch = i * 256 + tid;
            const int row = ch >> 2, c16 = ch & 3;
            CP_ASYNC16(ab + swz(row, c16 * 16),
                       Lop + (size_t)(row0 + row) * NMAT + kt * BK + c16 * 8);
            CP_ASYNC16(bb + swz(row, c16 * 16),
                       Rop + (size_t)(col0 + row) * NMAT + kt * BK + c16 * 8);
        }
    };

    fill(0, 0); CP_COMMIT();
    fill(1, 1); CP_COMMIT();
    fill(2, 2); CP_COMMIT();

    float acc[2][8][4];
#pragma unroll
    for (int mt = 0; mt < 2; mt++)
#pragma unroll
        for (int nt = 0; nt < 8; nt++)
#pragma unroll
            for (int j = 0; j < 4; j++) acc[mt][nt][j] = 0.f;

    for (int kt = 0; kt < KT; kt++) {
        CP_WAIT2();
        __syncthreads();

        const int s = kt & (STAGES - 1);
        const uint32_t ab = sb + s * STAGE_BYTES;
        const uint32_t bb = sb + SMEM_B_OFF + s * STAGE_BYTES;
#pragma unroll
        for (int st = 0; st < 2; st++) {               // two k16 steps per 32-K tile
            const int kb2 = st * 32;                   // col byte base
            uint32_t a[2][4], b[4][4];
#pragma unroll
            for (int mt = 0; mt < 2; mt++)
                LDSM_X4(a[mt][0], a[mt][1], a[mt][2], a[mt][3],
                        ab + swz(warp_m * 32 + mt * 16 + (lane & 15),
                                 kb2 + ((lane >> 4) << 4)));
#pragma unroll
            for (int np = 0; np < 4; np++)
                LDSM_X4(b[np][0], b[np][1], b[np][2], b[np][3],
                        bb + swz(warp_n * 64 + np * 16 + (lane & 7) + ((lane >> 4) << 3),
                                 kb2 + (((lane >> 3) & 1) << 4)));
#pragma unroll
            for (int mt = 0; mt < 2; mt++)
#pragma unroll
                for (int nt = 0; nt < 8; nt++) {
                    uint32_t bf[2] = {b[nt >> 1][(nt & 1) * 2], b[nt >> 1][(nt & 1) * 2 + 1]};
                    MMA_BF16(acc[mt][nt], a[mt], bf);
                }
        }

        const int f = kt + 3;
        if (f < KT) fill(f, f & (STAGES - 1));
        CP_COMMIT();
    }

    // ---------------- epilogue ----------------
#pragma unroll
    for (int mt = 0; mt < 2; mt++) {
        const int rA = row0 + warp_m * 32 + mt * 16 + (lane >> 2);  // rows rA, rA+8
        const float s0 = (MODE == 0) ? 4.0f : g_inv[rA];
        const float s1 = (MODE == 0) ? 4.0f : g_inv[rA + 8];
        float rs0 = 0.f, rs1 = 0.f;
#pragma unroll
        for (int nt = 0; nt < 8; nt++) {
            const int c = col0 + warp_n * 64 + nt * 8 + (lane & 3) * 2;
            float v0 = s0 * acc[mt][nt][0];
            float v1 = s0 * acc[mt][nt][1];
            float v2 = s1 * acc[mt][nt][2];
            float v3 = s1 * acc[mt][nt][3];
            if (MODE == 0) {
                if (rA == c)         v0 += 1.0f;
                if (rA == c + 1)     v1 += 1.0f;
                if (rA + 8 == c)     v2 += 1.0f;
                if (rA + 8 == c + 1) v3 += 1.0f;
                rs0 += v0 + v1;
                rs1 += v2 + v3;
                *reinterpret_cast<__nv_bfloat162*>(g_Hbf + (size_t)rA * NMAT + c) =
                    __floats2bfloat162_rn(v0, v1);
                *reinterpret_cast<__nv_bfloat162*>(g_Hbf + (size_t)(rA + 8) * NMAT + c) =
                    __floats2bfloat162_rn(v2, v3);
            } else {
                *reinterpret_cast<float2*>(Cout + (size_t)rA * NMAT + c) = make_float2(v0, v1);
                *reinterpret_cast<float2*>(Cout + (size_t)(rA + 8) * NMAT + c) = make_float2(v2, v3);
            }
        }
        if (MODE == 0) {
            rs0 += __shfl_xor_sync(0xFFFFFFFF, rs0, 1);
            rs0 += __shfl_xor_sync(0xFFFFFFFF, rs0, 2);
            rs1 += __shfl_xor_sync(0xFFFFFFFF, rs1, 1);
            rs1 += __shfl_xor_sync(0xFFFFFFFF, rs1, 2);
            if ((lane & 3) == 0) {
                g_rowpart[warp_n][blockIdx.x][rA] = rs0;
                g_rowpart[warp_n][blockIdx.x][rA + 8] = rs1;
            }
        }
    }
}

extern "C" void kernel_launch(void* const* d_in, const int* in_sizes, int n_in,
                              void* d_out, int out_size)
{
    const float* A = (const float*)d_in[0];   // weights unused: softmax over singleton == 1
    float* out = (float*)d_out;

    cudaFuncSetAttribute(gemm_mma<0>, cudaFuncAttributeMaxDynamicSharedMemorySize, SMEM_DYN);
    cudaFuncSetAttribute(gemm_mma<1>, cudaFuncAttributeMaxDynamicSharedMemorySize, SMEM_DYN);

    convert_kernel<<<dim3(NMAT / 32, NMAT / 32), dim3(32, 8)>>>(A);
    gemm_mma<0><<<dim3(NMAT / BN, NMAT / BM), 256, SMEM_DYN>>>(out);   // H = 4*A@A + I
    invdeg_kernel<<<NMAT / 256, 256>>>();
    gemm_mma<1><<<dim3(NMAT / BN, NMAT / BM), 256, SMEM_DYN>>>(out);   // out = diag(2/deg) @ (H@A)
}